// round 7
// baseline (speedup 1.0000x reference)
#include <cuda_runtime.h>
#include <cstdint>

// WarpedNonlinearity. Math (validated R1 @2.9e-7; TC pipeline validated R5 @2.5e-6):
//   4*y = silu(x) + silu(x*Su)*Sd + Su*( silu(Su^T*x) + silu((Su^T*x)*Su)*Sd )
// Su[n][j] = s[(j-n)&63], Sd = Su^T, s = half-sample sinc (circular, 64 taps).
//
// sm_103a: 6 GEMMs as tcgen05 kind::tf32 + 3xTF32 compensation, M=128 (2 images),
// N=K=64, SS mode. R6: 512 threads, paired parallel epilogues (D0-group || D1-group),
// merged commits -> 4 mbarrier waits. Plain sm_103 compat pass: FFMA fallback.

// ---- smem byte offsets (all MMA operands 1024B-aligned) ----
#define SM_TPTR 0
#define SM_MBAR 16
#define SM_S64  64
#define SM_BU   1024      // Bu  fp32 (hi via HW trunc)
#define SM_BUL  17408     // Bu lo
#define SM_BD   33792     // Bd  fp32
#define SM_BDL  50176     // Bd lo
#define SM_U0   66560     // x -> R0 (in place)
#define SM_U1   99328     // x_lo -> x10_lo
#define SM_U2   132096    // xT -> a01 -> a11 -> W^T
#define SM_U3   164864    // xT_lo -> a01_lo -> a11_lo -> W^T_lo
#define SM_U4   197632    // x10 fp32
#define SM_TOTAL 230400

#define IDESC_TF32 0x08100910u  // dF32 | aTF32 | bTF32 | (64/8)<<17 | (128/16)<<24

static constexpr uint64_t DESC_SW128 =
    (uint64_t(2) << 61) | (uint64_t(1) << 46) | (uint64_t(64) << 32) | (uint64_t(1) << 16);

__device__ __forceinline__ float silu_f(float v) {
    return __fdividef(v, 1.0f + __expf(-v));
}
__device__ __forceinline__ float lo13(float v) {   // v - tf32_truncate(v)
    return v - __uint_as_float(__float_as_uint(v) & 0xffffe000u);
}

#if defined(__CUDA_ARCH_FEAT_SM103_ALL)
// ===================== tcgen05 helpers (exact-arch cubin only) ======================

__device__ __forceinline__ uint32_t smem_u32(const void* p) {
    uint32_t a;
    asm("{ .reg .u64 t; cvta.to.shared.u64 t, %1; cvt.u32.u64 %0, t; }" : "=r"(a) : "l"(p));
    return a;
}
__device__ __forceinline__ uint32_t elect1() {
    uint32_t r;
    asm volatile("{ .reg .pred p; elect.sync _|p, 0xFFFFFFFF; selp.b32 %0,1,0,p; }" : "=r"(r));
    return r;
}
__device__ __forceinline__ uint32_t amap(uint32_t r, uint32_t c) {  // 128-row SW128 K-major
    uint32_t b = ((r >> 3) + (c >> 5) * 16u) * 1024u + (r & 7u) * 128u + (c & 31u) * 4u;
    return b ^ ((b >> 3) & 0x70u);
}
__device__ __forceinline__ uint32_t bmap(uint32_t j, uint32_t k) {  // 64-row SW128 K-major
    uint32_t b = ((j >> 3) + (k >> 5) * 8u) * 1024u + (j & 7u) * 128u + (k & 31u) * 4u;
    return b ^ ((b >> 3) & 0x70u);
}

#define MBARRIER_INIT(a, n) \
    asm volatile("mbarrier.init.shared.b64 [%0], %1;" :: "r"((uint32_t)(a)), "r"((uint32_t)(n)) : "memory")
#define MBARRIER_INVAL(a) \
    asm volatile("mbarrier.inval.shared.b64 [%0];" :: "r"((uint32_t)(a)) : "memory")
#define MBARRIER_WAIT_PARITY(mb, par) do { \
    uint32_t _m = (uint32_t)(mb), _p = (uint32_t)(par), _d; \
    asm volatile("{\n\t.reg .pred p;\n\t" \
        "mbarrier.try_wait.parity.acquire.cta.shared::cta.b64 p, [%1], %2;\n\t" \
        "selp.b32 %0, 1, 0, p;\n\t}" : "=r"(_d) : "r"(_m), "r"(_p) : "memory"); \
    if (!_d) { \
        asm volatile("{\n\t.reg .pred P1;\n\t" \
            "WL_%=:\n\t" \
            "mbarrier.try_wait.parity.acquire.cta.shared::cta.b64 P1, [%0], %1, 0x989680;\n\t" \
            "@P1 bra.uni WD_%=;\n\tbra.uni WL_%=;\n\tWD_%=:\n\t}" \
            :: "r"(_m), "r"(_p) : "memory"); \
    } } while (0)

#define TCGEN05_ALLOC(a, n) \
    asm volatile("tcgen05.alloc.cta_group::1.sync.aligned.shared::cta.b32 [%0], %1;" \
                 :: "r"((uint32_t)(a)), "r"((uint32_t)(n)) : "memory")
#define TCGEN05_DEALLOC(t, n) \
    asm volatile("tcgen05.dealloc.cta_group::1.sync.aligned.b32 %0, %1;" :: "r"(t), "r"((uint32_t)(n)))
#define TCGEN05_RELINQ() \
    asm volatile("tcgen05.relinquish_alloc_permit.cta_group::1.sync.aligned;")
#define TCGEN05_COMMIT(mb) \
    asm volatile("tcgen05.commit.cta_group::1.mbarrier::arrive::one.shared::cluster.b64 [%0];" \
                 :: "r"((uint32_t)(mb)) : "memory")
#define TCGEN05_WAIT_LD()  asm volatile("tcgen05.wait::ld.sync.aligned;" ::: "memory")
#define TCGEN05_FENCE_BEFORE() asm volatile("tcgen05.fence::before_thread_sync;" ::: "memory")
#define TCGEN05_FENCE_AFTER()  asm volatile("tcgen05.fence::after_thread_sync;" ::: "memory")
#define FENCE_PROXY_ASYNC() asm volatile("fence.proxy.async.shared::cta;" ::: "memory")

#define LDTM_X32(r, addr) \
    asm volatile("tcgen05.ld.sync.aligned.32x32b.x32.b32 " \
        "{%0, %1, %2, %3, %4, %5, %6, %7, %8, %9, %10, %11, %12, %13, %14, %15, " \
        " %16, %17, %18, %19, %20, %21, %22, %23, %24, %25, %26, %27, %28, %29, %30, %31}, [%32];" \
        : "=r"((r)[0]),  "=r"((r)[1]),  "=r"((r)[2]),  "=r"((r)[3]), \
          "=r"((r)[4]),  "=r"((r)[5]),  "=r"((r)[6]),  "=r"((r)[7]), \
          "=r"((r)[8]),  "=r"((r)[9]),  "=r"((r)[10]), "=r"((r)[11]), \
          "=r"((r)[12]), "=r"((r)[13]), "=r"((r)[14]), "=r"((r)[15]), \
          "=r"((r)[16]), "=r"((r)[17]), "=r"((r)[18]), "=r"((r)[19]), \
          "=r"((r)[20]), "=r"((r)[21]), "=r"((r)[22]), "=r"((r)[23]), \
          "=r"((r)[24]), "=r"((r)[25]), "=r"((r)[26]), "=r"((r)[27]), \
          "=r"((r)[28]), "=r"((r)[29]), "=r"((r)[30]), "=r"((r)[31]) \
        : "r"(addr))

#define LDTM_X16(r, addr) \
    asm volatile("tcgen05.ld.sync.aligned.32x32b.x16.b32 " \
        "{%0, %1, %2, %3, %4, %5, %6, %7, %8, %9, %10, %11, %12, %13, %14, %15}, [%16];" \
        : "=r"((r)[0]),  "=r"((r)[1]),  "=r"((r)[2]),  "=r"((r)[3]), \
          "=r"((r)[4]),  "=r"((r)[5]),  "=r"((r)[6]),  "=r"((r)[7]), \
          "=r"((r)[8]),  "=r"((r)[9]),  "=r"((r)[10]), "=r"((r)[11]), \
          "=r"((r)[12]), "=r"((r)[13]), "=r"((r)[14]), "=r"((r)[15]) \
        : "r"(addr))

// K=64 as 8 MMAs of K=8 tf32; en0 = accumulate-flag of the first step.
__device__ __forceinline__ void mma8(uint32_t d, uint32_t a_s, uint32_t b_s, uint32_t en0) {
    uint64_t ad = DESC_SW128 | ((uint64_t)(a_s >> 4) & 0x3FFF);
    uint64_t bd = DESC_SW128 | ((uint64_t)(b_s >> 4) & 0x3FFF);
#pragma unroll
    for (int k = 0; k < 8; k++) {
        uint64_t ao = (uint64_t)((k >> 2) * 1024 + (k & 3) * 2);
        uint64_t bo = (uint64_t)((k >> 2) * 512 + (k & 3) * 2);
        uint32_t en = (k > 0) ? 1u : en0;
        asm volatile(
            "{\n\t.reg .pred p;\n\tsetp.ne.u32 p, %4, 0;\n\t"
            "tcgen05.mma.cta_group::1.kind::tf32 [%0], %1, %2, %3, {%5, %5, %5, %5}, p;\n\t}"
            :: "r"(d), "l"(ad + ao), "l"(bd + bo), "r"(IDESC_TF32), "r"(en), "r"(0u)
            : "memory");
    }
}
// 3xTF32: D = A*B + Alo*B + A*Blo   (fp32-grade precision)
__device__ __forceinline__ void gemm3(uint32_t d, uint32_t a, uint32_t alo,
                                      uint32_t b, uint32_t blo) {
    mma8(d, a, b, 0);
    mma8(d, alo, b, 1);
    mma8(d, a, blo, 1);
}
#endif  // feature guard (device helpers)

__global__ void __launch_bounds__(512, 1)
warped_kernel(const float* __restrict__ x, float* __restrict__ y) {
#if defined(__CUDA_ARCH_FEAT_SM103_ALL)
    // ======================= tensor-core body (16 warps) =======================
    extern __shared__ char sm[];
    const uint32_t sb = smem_u32(sm);
    const int tid = threadIdx.x;
    const int lane = tid & 31;
    const int w = tid >> 5;                 // 0..15
    const int grpB = (w >> 3);              // 0: D0-group, 1: D1-group
    const int wl = w & 7;                   // warp index within group
    const int mg = (wl & 3) * 32 + lane;    // TMEM lane for group epilogues
    const int cbg = (wl >> 2) * 32;         // 32-col half for group epilogues
    const int ma = (w & 3) * 32 + lane;     // TMEM lane for all-warp epilogues
    const int cba = (w >> 2) * 16;          // 16-col quarter for all-warp epilogues

    if (w == 0) TCGEN05_ALLOC(sb + SM_TPTR, 128);
    if (tid == 0) MBARRIER_INIT(sb + SM_MBAR, 1);

    if (tid < 64) {
        float q = (float)(2 * tid + 1);
        *(float*)(sm + SM_S64 + tid * 4) =
            sinpif(63.0f * q * (1.0f / 128.0f)) / (64.0f * sinpif(q * (1.0f / 128.0f)));
    }
    __syncthreads();
    uint32_t tb;
    asm volatile("ld.shared.b32 %0, [%1];" : "=r"(tb) : "r"(sb + SM_TPTR));
    const uint32_t D0 = tb, D1 = tb + 64;

    // circulants (MMA computes A*B^T): Bu[j][k]=s[(j-k)&63], Bd[j][k]=s[(j-k-1)&63], + lo's
    const float* s64 = (const float*)(sm + SM_S64);
#pragma unroll
    for (int i = 0; i < 8; i++) {
        int idx = tid + 512 * i;
        int j = idx >> 6, k = idx & 63;
        uint32_t o = bmap(j, k);
        float su = s64[(j - k) & 63];
        float sd = s64[(j - k - 1) & 63];
        *(float*)(sm + SM_BU + o)  = su;
        *(float*)(sm + SM_BUL + o) = lo13(su);
        *(float*)(sm + SM_BD + o)  = sd;
        *(float*)(sm + SM_BDL + o) = lo13(sd);
    }

    // load 2 images: x -> U0 (+lo U1), per-image transpose -> U2 (+lo U3)
    const float4* xg = (const float4*)(x + (size_t)blockIdx.x * 8192);
#pragma unroll
    for (int i = 0; i < 4; i++) {
        int f = tid + 512 * i;
        int mr = f >> 4, c4 = (f & 15) << 2;
        float4 v = xg[f];
        float4 lo;
        lo.x = lo13(v.x); lo.y = lo13(v.y); lo.z = lo13(v.z); lo.w = lo13(v.w);
        *(float4*)(sm + SM_U0 + amap(mr, c4)) = v;
        *(float4*)(sm + SM_U1 + amap(mr, c4)) = lo;
        int rowb = (mr >> 6) * 64, colr = mr & 63;
        *(float*)(sm + SM_U2 + amap(rowb + c4 + 0, colr)) = v.x;
        *(float*)(sm + SM_U2 + amap(rowb + c4 + 1, colr)) = v.y;
        *(float*)(sm + SM_U2 + amap(rowb + c4 + 2, colr)) = v.z;
        *(float*)(sm + SM_U2 + amap(rowb + c4 + 3, colr)) = v.w;
        *(float*)(sm + SM_U3 + amap(rowb + c4 + 0, colr)) = lo.x;
        *(float*)(sm + SM_U3 + amap(rowb + c4 + 1, colr)) = lo.y;
        *(float*)(sm + SM_U3 + amap(rowb + c4 + 2, colr)) = lo.z;
        *(float*)(sm + SM_U3 + amap(rowb + c4 + 3, colr)) = lo.w;
    }
    FENCE_PROXY_ASYNC();
    __syncthreads();

    int ph = 0;
    // G1: D0 = x*Su ; G3: D1 = x10^T = xT*Su   (one commit)
    if (w == 0 && elect1()) {
        gemm3(D0, sb + SM_U0, sb + SM_U1, sb + SM_BU, sb + SM_BUL);
        gemm3(D1, sb + SM_U2, sb + SM_U3, sb + SM_BU, sb + SM_BUL);
        TCGEN05_COMMIT(sb + SM_MBAR);
    }
    MBARRIER_WAIT_PARITY(sb + SM_MBAR, ph); ph ^= 1;
    TCGEN05_FENCE_AFTER();

    // E1 (group A): a01 = silu(D0) -> U2 (+lo U3)   [xT dead after G3]
    // E3 (group B): x10 raw (de-transposed) -> U4 (+lo U1)  [x_lo dead after G1]
    if (!grpB) {
        uint32_t r[32];
        LDTM_X32(r, D0 + cbg);
        TCGEN05_WAIT_LD();
#pragma unroll
        for (int q = 0; q < 8; q++) {
            float4 v, lo;
            v.x = silu_f(__uint_as_float(r[4 * q + 0]));
            v.y = silu_f(__uint_as_float(r[4 * q + 1]));
            v.z = silu_f(__uint_as_float(r[4 * q + 2]));
            v.w = silu_f(__uint_as_float(r[4 * q + 3]));
            lo.x = lo13(v.x); lo.y = lo13(v.y); lo.z = lo13(v.z); lo.w = lo13(v.w);
            uint32_t a = amap(mg, cbg + 4 * q);
            *(float4*)(sm + SM_U2 + a) = v;
            *(float4*)(sm + SM_U3 + a) = lo;
        }
    } else {
        uint32_t r[32];
        LDTM_X32(r, D1 + cbg);
        TCGEN05_WAIT_LD();
        int rowb = (mg >= 64) ? 64 : 0;
        int colm = mg & 63;
#pragma unroll
        for (int c = 0; c < 32; c++) {
            float xv = __uint_as_float(r[c]);
            uint32_t a = amap(rowb + cbg + c, colm);
            *(float*)(sm + SM_U4 + a) = xv;
            *(float*)(sm + SM_U1 + a) = lo13(xv);
        }
    }
    TCGEN05_FENCE_BEFORE();
    FENCE_PROXY_ASYNC();
    __syncthreads();

    // G2: D0 = a01*Sd ; G4: D1 = x10*Su   (one commit)
    if (w == 0 && elect1()) {
        gemm3(D0, sb + SM_U2, sb + SM_U3, sb + SM_BD, sb + SM_BDL);
        gemm3(D1, sb + SM_U4, sb + SM_U1, sb + SM_BU, sb + SM_BUL);
        TCGEN05_COMMIT(sb + SM_MBAR);
    }
    MBARRIER_WAIT_PARITY(sb + SM_MBAR, ph); ph ^= 1;
    TCGEN05_FENCE_AFTER();

    // E2 (group A): R0 = silu(x) + D0, in place in U0
    // E4 (group B): a11 = silu(D1) -> U2 (+lo U3)   [a01 dead after G2]
    if (!grpB) {
        uint32_t r[32];
        LDTM_X32(r, D0 + cbg);
        TCGEN05_WAIT_LD();
#pragma unroll
        for (int q = 0; q < 8; q++) {
            uint32_t a = amap(mg, cbg + 4 * q);
            float4 xv = *(float4*)(sm + SM_U0 + a);
            float4 v;
            v.x = silu_f(xv.x) + __uint_as_float(r[4 * q + 0]);
            v.y = silu_f(xv.y) + __uint_as_float(r[4 * q + 1]);
            v.z = silu_f(xv.z) + __uint_as_float(r[4 * q + 2]);
            v.w = silu_f(xv.w) + __uint_as_float(r[4 * q + 3]);
            *(float4*)(sm + SM_U0 + a) = v;
        }
    } else {
        uint32_t r[32];
        LDTM_X32(r, D1 + cbg);
        TCGEN05_WAIT_LD();
#pragma unroll
        for (int q = 0; q < 8; q++) {
            float4 v, lo;
            v.x = silu_f(__uint_as_float(r[4 * q + 0]));
            v.y = silu_f(__uint_as_float(r[4 * q + 1]));
            v.z = silu_f(__uint_as_float(r[4 * q + 2]));
            v.w = silu_f(__uint_as_float(r[4 * q + 3]));
            lo.x = lo13(v.x); lo.y = lo13(v.y); lo.z = lo13(v.z); lo.w = lo13(v.w);
            uint32_t a = amap(mg, cbg + 4 * q);
            *(float4*)(sm + SM_U2 + a) = v;
            *(float4*)(sm + SM_U3 + a) = lo;
        }
    }
    TCGEN05_FENCE_BEFORE();
    FENCE_PROXY_ASYNC();
    __syncthreads();

    // G5: D0 = a11*Sd   (D0 free: E2's reads done at sync)
    if (w == 0 && elect1()) {
        gemm3(D0, sb + SM_U2, sb + SM_U3, sb + SM_BD, sb + SM_BDL);
        TCGEN05_COMMIT(sb + SM_MBAR);
    }
    MBARRIER_WAIT_PARITY(sb + SM_MBAR, ph); ph ^= 1;
    TCGEN05_FENCE_AFTER();

    // E5 (all warps, 16 cols each): W = D0 + silu(x10); store W^T -> U2 (+lo U3)
    {
        uint32_t r[16];
        LDTM_X16(r, D0 + cba);
        TCGEN05_WAIT_LD();
        int rowb = (ma >= 64) ? 64 : 0;
        int colm = ma & 63;
#pragma unroll
        for (int q = 0; q < 4; q++) {
            float4 xv = *(float4*)(sm + SM_U4 + amap(ma, cba + 4 * q));
            float wv[4];
            wv[0] = __uint_as_float(r[4 * q + 0]) + silu_f(xv.x);
            wv[1] = __uint_as_float(r[4 * q + 1]) + silu_f(xv.y);
            wv[2] = __uint_as_float(r[4 * q + 2]) + silu_f(xv.z);
            wv[3] = __uint_as_float(r[4 * q + 3]) + silu_f(xv.w);
#pragma unroll
            for (int t = 0; t < 4; t++) {
                uint32_t a = amap(rowb + cba + 4 * q + t, colm);
                *(float*)(sm + SM_U2 + a) = wv[t];
                *(float*)(sm + SM_U3 + a) = lo13(wv[t]);
            }
        }
    }
    TCGEN05_FENCE_BEFORE();
    FENCE_PROXY_ASYNC();
    __syncthreads();

    // G6: D1 = W^T*Sd  ( = (Su*W)^T )
    if (w == 0 && elect1()) {
        gemm3(D1, sb + SM_U2, sb + SM_U3, sb + SM_BD, sb + SM_BDL);
        TCGEN05_COMMIT(sb + SM_MBAR);
    }
    MBARRIER_WAIT_PARITY(sb + SM_MBAR, ph); ph ^= 1;
    TCGEN05_FENCE_AFTER();

    // E6 (all warps): y = 0.25*(R0 + branch2), branch2[n][j] = D1[img*64+j][n]
    {
        uint32_t r[16];
        LDTM_X16(r, D1 + cba);
        TCGEN05_WAIT_LD();
        int img = (ma >= 64) ? 1 : 0;
        int colm = ma & 63;
        float* yg = y + ((size_t)blockIdx.x * 2 + img) * 4096;
#pragma unroll
        for (int c = 0; c < 16; c++) {
            int j = cba + c;
            float r0 = *(const float*)(sm + SM_U0 + amap(img * 64 + j, colm));
            yg[j * 64 + colm] = 0.25f * (__uint_as_float(r[c]) + r0);
        }
    }
    TCGEN05_FENCE_BEFORE();
    __syncthreads();
    if (tid == 0) MBARRIER_INVAL(sb + SM_MBAR);
    __syncthreads();
    if (w == 0) {
        TCGEN05_RELINQ();
        TCGEN05_DEALLOC(tb, 128);
    }

#else
    // ====== FFMA fallback (compat PTX pass only; never runs on GB300) ======
    // 512 threads, 2x4 register tiles, 2 images sequentially.
#define FSTRIDE 68
    extern __shared__ float fsm[];
    float* Su  = fsm;
    float* Sd  = Su + 64 * FSTRIDE;
    float* bx  = Sd + 64 * FSTRIDE;
    float* tbf = bx + 64 * FSTRIDE;
    float* ub  = tbf + 64 * FSTRIDE;
    float* s64 = ub + 64 * FSTRIDE;

    const int tid = threadIdx.x;
    const int ti2 = (tid >> 4) << 1;      // 2-row group (0..62)
    const int tj4 = (tid & 15) << 2;      // 4-col group

    if (tid < 64) {
        float q = (float)(2 * tid + 1);
        s64[tid] = sinpif(63.0f * q * (1.0f / 128.0f)) /
                   (64.0f * sinpif(q * (1.0f / 128.0f)));
    }
    __syncthreads();
    for (int idx = tid; idx < 4096; idx += 512) {
        int n = idx >> 6, j = idx & 63;
        Su[n * FSTRIDE + j] = s64[(j - n) & 63];
        Sd[n * FSTRIDE + j] = s64[(j - n - 1) & 63];
    }
    __syncthreads();

    for (int img = 0; img < 2; img++) {
        const float* xin = x + ((size_t)blockIdx.x * 2 + img) * 4096;
        float* yout      = y + ((size_t)blockIdx.x * 2 + img) * 4096;
        for (int idx = tid; idx < 1024; idx += 512) {
            float4 v = ((const float4*)xin)[idx];
            *(float4*)(bx + (idx >> 4) * FSTRIDE + ((idx & 15) << 2)) = v;
        }
        __syncthreads();

        float acc[2][4], cc[2][4];
#pragma unroll
        for (int r = 0; r < 2; r++)
#pragma unroll
            for (int c = 0; c < 4; c++)
                acc[r][c] = silu_f(bx[(ti2 + r) * FSTRIDE + tj4 + c]);

#pragma unroll
        for (int r = 0; r < 2; r++)
#pragma unroll
            for (int c = 0; c < 4; c++) cc[r][c] = 0.0f;
        for (int k = 0; k < 64; k++) {
#pragma unroll
            for (int r = 0; r < 2; r++) {
                float av = bx[(ti2 + r) * FSTRIDE + k];
#pragma unroll
                for (int c = 0; c < 4; c++)
                    cc[r][c] = fmaf(av, Su[k * FSTRIDE + tj4 + c], cc[r][c]);
            }
        }
#pragma unroll
        for (int r = 0; r < 2; r++)
#pragma unroll
            for (int c = 0; c < 4; c++)
                tbf[(ti2 + r) * FSTRIDE + tj4 + c] = silu_f(cc[r][c]);
        __syncthreads();

#pragma unroll
        for (int r = 0; r < 2; r++)
#pragma unroll
            for (int c = 0; c < 4; c++) cc[r][c] = 0.0f;
        for (int k = 0; k < 64; k++) {
#pragma unroll
            for (int r = 0; r < 2; r++) {
                float av = tbf[(ti2 + r) * FSTRIDE + k];
                float bv = Su[k * FSTRIDE + ti2 + r];
#pragma unroll
                for (int c = 0; c < 4; c++) {
                    acc[r][c] = fmaf(av, Sd[k * FSTRIDE + tj4 + c], acc[r][c]);
                    cc[r][c] = fmaf(bv, bx[k * FSTRIDE + tj4 + c], cc[r][c]);
                }
            }
        }
#pragma unroll
        for (int r = 0; r < 2; r++)
#pragma unroll
            for (int c = 0; c < 4; c++)
                ub[(ti2 + r) * FSTRIDE + tj4 + c] = cc[r][c];
        __syncthreads();

#pragma unroll
        for (int r = 0; r < 2; r++)
#pragma unroll
            for (int c = 0; c < 4; c++) cc[r][c] = 0.0f;
        for (int k = 0; k < 64; k++) {
#pragma unroll
            for (int r = 0; r < 2; r++) {
                float av = ub[(ti2 + r) * FSTRIDE + k];
#pragma unroll
                for (int c = 0; c < 4; c++)
                    cc[r][c] = fmaf(av, Su[k * FSTRIDE + tj4 + c], cc[r][c]);
            }
        }
#pragma unroll
        for (int r = 0; r < 2; r++)
#pragma unroll
            for (int c = 0; c < 4; c++)
                tbf[(ti2 + r) * FSTRIDE + tj4 + c] = silu_f(cc[r][c]);
        __syncthreads();

#pragma unroll
        for (int r = 0; r < 2; r++)
#pragma unroll
            for (int c = 0; c < 4; c++) cc[r][c] = 0.0f;
        for (int k = 0; k < 64; k++) {
#pragma unroll
            for (int r = 0; r < 2; r++) {
                float av = tbf[(ti2 + r) * FSTRIDE + k];
#pragma unroll
                for (int c = 0; c < 4; c++)
                    cc[r][c] = fmaf(av, Sd[k * FSTRIDE + tj4 + c], cc[r][c]);
            }
        }
        __syncthreads();
#pragma unroll
        for (int r = 0; r < 2; r++)
#pragma unroll
            for (int c = 0; c < 4; c++)
                bx[(ti2 + r) * FSTRIDE + tj4 + c] =
                    cc[r][c] + silu_f(ub[(ti2 + r) * FSTRIDE + tj4 + c]);
        __syncthreads();

        for (int k = 0; k < 64; k++) {
#pragma unroll
            for (int r = 0; r < 2; r++) {
                float av = Su[(ti2 + r) * FSTRIDE + k];
#pragma unroll
                for (int c = 0; c < 4; c++)
                    acc[r][c] = fmaf(av, bx[k * FSTRIDE + tj4 + c], acc[r][c]);
            }
        }
#pragma unroll
        for (int r = 0; r < 2; r++) {
            float4 v;
            v.x = 0.25f * acc[r][0]; v.y = 0.25f * acc[r][1];
            v.z = 0.25f * acc[r][2]; v.w = 0.25f * acc[r][3];
            *(float4*)(yout + (ti2 + r) * 64 + tj4) = v;
        }
        __syncthreads();
    }
#endif
}

extern "C" void kernel_launch(void* const* d_in, const int* in_sizes, int n_in,
                              void* d_out, int out_size) {
    const float* x = (const float*)d_in[0];
    float* y = (float*)d_out;
    const int n_img = in_sizes[0] / 4096;      // 2048
    cudaFuncSetAttribute(warped_kernel,
                         cudaFuncAttributeMaxDynamicSharedMemorySize, SM_TOTAL);
    warped_kernel<<<n_img / 2, 512, SM_TOTAL>>>(x, y);
}

// round 8
// speedup vs baseline: 1.0221x; 1.0221x over previous
#include <cuda_runtime.h>
#include <cuda_bf16.h>
#include <cstdint>

// WarpedNonlinearity (math validated R1/R5):
//   4*y = silu(x) + silu(x*Su)*Sd + Su*( silu(Su^T*x) + silu((Su^T*x)*Su)*Sd )
// R7: bf16-split (hi/lo planes, 3 passes kind::f16) halves SMEM; two independent
// 8-warp chains per CTA (4 images), each with own mbar/named-bar/TMEM half.

#define SM_TPTR  0
#define SM_MBAR0 16          // +16*chain
#define SM_S64   64
#define SM_BUH   1024
#define SM_BUL   9216
#define SM_BDH   17408
#define SM_BDL   25600
#define SM_CH0   33792
#define CH_SZ    98304
#define P_S0H 0              // x hi -> R0 hi (in place)
#define P_S0L 16384
#define P_S1H 32768          // xT -> a01 -> a11 -> W^T  (hi)
#define P_S1L 49152
#define P_S2H 65536          // x10 hi
#define P_S2L 81920
#define SM_TOTAL 230400

#define IDESC_BF16 0x8100490u  // f32 acc | aBF16 | bBF16 | (64/8)<<17 | (128/16)<<24

static constexpr uint64_t DESC_SW128 =
    (uint64_t(2) << 61) | (uint64_t(1) << 46) | (uint64_t(64) << 32) | (uint64_t(1) << 16);

__device__ __forceinline__ float silu_f(float v) {
    return __fdividef(v, 1.0f + __expf(-v));
}

#if defined(__CUDA_ARCH_FEAT_SM103_ALL)
__device__ __forceinline__ uint32_t smem_u32(const void* p) {
    uint32_t a;
    asm("{ .reg .u64 t; cvta.to.shared.u64 t, %1; cvt.u32.u64 %0, t; }" : "=r"(a) : "l"(p));
    return a;
}
__device__ __forceinline__ uint32_t elect1() {
    uint32_t r;
    asm volatile("{ .reg .pred p; elect.sync _|p, 0xFFFFFFFF; selp.b32 %0,1,0,p; }" : "=r"(r));
    return r;
}
// bf16 K-major SW128, K=64 (=128B row, single atom column)
__device__ __forceinline__ uint32_t amap16(uint32_t r, uint32_t c) {
    return (r * 128u + 2u * c) ^ ((r & 7u) << 4);
}
__device__ __forceinline__ void bsplit(float v, __nv_bfloat16& h, __nv_bfloat16& l) {
    h = __float2bfloat16(v);
    l = __float2bfloat16(v - __bfloat162float(h));
}
__device__ __forceinline__ float bjoin(const char* sm, uint32_t hioff, uint32_t looff, uint32_t a) {
    return __bfloat162float(*(const __nv_bfloat16*)(sm + hioff + a)) +
           __bfloat162float(*(const __nv_bfloat16*)(sm + looff + a));
}

#define MBARRIER_INIT(a, n) \
    asm volatile("mbarrier.init.shared.b64 [%0], %1;" :: "r"((uint32_t)(a)), "r"((uint32_t)(n)) : "memory")
#define MBARRIER_INVAL(a) \
    asm volatile("mbarrier.inval.shared.b64 [%0];" :: "r"((uint32_t)(a)) : "memory")
#define MBARRIER_WAIT_PARITY(mb, par) do { \
    uint32_t _m = (uint32_t)(mb), _p = (uint32_t)(par), _d; \
    asm volatile("{\n\t.reg .pred p;\n\t" \
        "mbarrier.try_wait.parity.acquire.cta.shared::cta.b64 p, [%1], %2;\n\t" \
        "selp.b32 %0, 1, 0, p;\n\t}" : "=r"(_d) : "r"(_m), "r"(_p) : "memory"); \
    if (!_d) { \
        asm volatile("{\n\t.reg .pred P1;\n\t" \
            "WL_%=:\n\t" \
            "mbarrier.try_wait.parity.acquire.cta.shared::cta.b64 P1, [%0], %1, 0x989680;\n\t" \
            "@P1 bra.uni WD_%=;\n\tbra.uni WL_%=;\n\tWD_%=:\n\t}" \
            :: "r"(_m), "r"(_p) : "memory"); \
    } } while (0)

#define TCGEN05_ALLOC(a, n) \
    asm volatile("tcgen05.alloc.cta_group::1.sync.aligned.shared::cta.b32 [%0], %1;" \
                 :: "r"((uint32_t)(a)), "r"((uint32_t)(n)) : "memory")
#define TCGEN05_DEALLOC(t, n) \
    asm volatile("tcgen05.dealloc.cta_group::1.sync.aligned.b32 %0, %1;" :: "r"(t), "r"((uint32_t)(n)))
#define TCGEN05_RELINQ() \
    asm volatile("tcgen05.relinquish_alloc_permit.cta_group::1.sync.aligned;")
#define TCGEN05_COMMIT(mb) \
    asm volatile("tcgen05.commit.cta_group::1.mbarrier::arrive::one.shared::cluster.b64 [%0];" \
                 :: "r"((uint32_t)(mb)) : "memory")
#define TCGEN05_WAIT_LD()  asm volatile("tcgen05.wait::ld.sync.aligned;" ::: "memory")
#define TCGEN05_FENCE_BEFORE() asm volatile("tcgen05.fence::before_thread_sync;" ::: "memory")
#define TCGEN05_FENCE_AFTER()  asm volatile("tcgen05.fence::after_thread_sync;" ::: "memory")
#define FENCE_PROXY_ASYNC() asm volatile("fence.proxy.async.shared::cta;" ::: "memory")
#define CHAIN_BAR(c) asm volatile("bar.sync %0, 256;" :: "r"(1 + (c)) : "memory")

#define LDTM_X32(r, addr) \
    asm volatile("tcgen05.ld.sync.aligned.32x32b.x32.b32 " \
        "{%0, %1, %2, %3, %4, %5, %6, %7, %8, %9, %10, %11, %12, %13, %14, %15, " \
        " %16, %17, %18, %19, %20, %21, %22, %23, %24, %25, %26, %27, %28, %29, %30, %31}, [%32];" \
        : "=r"((r)[0]),  "=r"((r)[1]),  "=r"((r)[2]),  "=r"((r)[3]), \
          "=r"((r)[4]),  "=r"((r)[5]),  "=r"((r)[6]),  "=r"((r)[7]), \
          "=r"((r)[8]),  "=r"((r)[9]),  "=r"((r)[10]), "=r"((r)[11]), \
          "=r"((r)[12]), "=r"((r)[13]), "=r"((r)[14]), "=r"((r)[15]), \
          "=r"((r)[16]), "=r"((r)[17]), "=r"((r)[18]), "=r"((r)[19]), \
          "=r"((r)[20]), "=r"((r)[21]), "=r"((r)[22]), "=r"((r)[23]), \
          "=r"((r)[24]), "=r"((r)[25]), "=r"((r)[26]), "=r"((r)[27]), \
          "=r"((r)[28]), "=r"((r)[29]), "=r"((r)[30]), "=r"((r)[31]) \
        : "r"(addr))

// one K=64 bf16 pass = 4 MMAs of K=16
__device__ __forceinline__ void mma4(uint32_t d, uint32_t a_s, uint32_t b_s, uint32_t en0) {
    uint64_t ad = DESC_SW128 | ((uint64_t)(a_s >> 4) & 0x3FFF);
    uint64_t bd = DESC_SW128 | ((uint64_t)(b_s >> 4) & 0x3FFF);
#pragma unroll
    for (int k = 0; k < 4; k++) {
        uint32_t en = (k > 0) ? 1u : en0;
        asm volatile(
            "{\n\t.reg .pred p;\n\tsetp.ne.u32 p, %4, 0;\n\t"
            "tcgen05.mma.cta_group::1.kind::f16 [%0], %1, %2, %3, {%5, %5, %5, %5}, p;\n\t}"
            :: "r"(d), "l"(ad + 2 * k), "l"(bd + 2 * k), "r"(IDESC_BF16), "r"(en), "r"(0u)
            : "memory");
    }
}
// bf16-split GEMM: D = Ah*Bh + Al*Bh + Ah*Bl
__device__ __forceinline__ void gemm3(uint32_t d, uint32_t ah, uint32_t al,
                                      uint32_t bh, uint32_t bl) {
    mma4(d, ah, bh, 0);
    mma4(d, al, bh, 1);
    mma4(d, ah, bl, 1);
}
#endif

__global__ void __launch_bounds__(512, 1)
warped_kernel(const float* __restrict__ x, float* __restrict__ y) {
#if defined(__CUDA_ARCH_FEAT_SM103_ALL)
    extern __shared__ char sm[];
    const uint32_t sb = smem_u32(sm);
    const int tid = threadIdx.x;
    const int lane = tid & 31;
    const int w = tid >> 5;            // 0..15
    const int chain = w >> 3;          // 0/1
    const int wl = w & 7;              // warp in chain
    const int mg = (wl & 3) * 32 + lane;   // TMEM lane (subpartition = w%4 = wl%4)
    const int cbg = (wl >> 2) * 32;        // col half for 8-warp epilogues

    const uint32_t CHo = SM_CH0 + (uint32_t)chain * CH_SZ;
    const uint32_t S0H = CHo + P_S0H, S0L = CHo + P_S0L;
    const uint32_t S1H = CHo + P_S1H, S1L = CHo + P_S1L;
    const uint32_t S2H = CHo + P_S2H, S2L = CHo + P_S2L;
    const uint32_t MB = sb + SM_MBAR0 + chain * 16;

    if (w == 0) TCGEN05_ALLOC(sb + SM_TPTR, 256);
    if (tid == 0) { MBARRIER_INIT(sb + SM_MBAR0, 1); MBARRIER_INIT(sb + SM_MBAR0 + 16, 1); }
    if (tid < 64) {
        float q = (float)(2 * tid + 1);
        *(float*)(sm + SM_S64 + tid * 4) =
            sinpif(63.0f * q * (1.0f / 128.0f)) / (64.0f * sinpif(q * (1.0f / 128.0f)));
    }
    __syncthreads();
    uint32_t tb;
    asm volatile("ld.shared.b32 %0, [%1];" : "=r"(tb) : "r"(sb + SM_TPTR));
    const uint32_t D0 = tb + chain * 128, D1 = D0 + 64;

    // circulants hi/lo: Bu[j][k]=s[(j-k)&63], Bd[j][k]=s[(j-k-1)&63]
    {
        const float* s64 = (const float*)(sm + SM_S64);
#pragma unroll
        for (int i = 0; i < 8; i++) {
            int idx = tid + 512 * i;
            int j = idx >> 6, k = idx & 63;
            uint32_t o = amap16(j, k);
            __nv_bfloat16 h, l;
            bsplit(s64[(j - k) & 63], h, l);
            *(__nv_bfloat16*)(sm + SM_BUH + o) = h;
            *(__nv_bfloat16*)(sm + SM_BUL + o) = l;
            bsplit(s64[(j - k - 1) & 63], h, l);
            *(__nv_bfloat16*)(sm + SM_BDH + o) = h;
            *(__nv_bfloat16*)(sm + SM_BDL + o) = l;
        }
    }

    // load 4 images: per chain block, x row-form -> S0, xT -> S1 (hi/lo)
    const float4* xg = (const float4*)(x + (size_t)blockIdx.x * 16384);
#pragma unroll
    for (int i = 0; i < 8; i++) {
        int f = tid + 512 * i;
        uint32_t CB = SM_CH0 + (uint32_t)(f >> 11) * CH_SZ;
        int g = f & 2047;
        int mr = g >> 4, c4 = (g & 15) << 2;
        float4 v = xg[f];
        __nv_bfloat16 h0, l0, h1, l1, h2, l2, h3, l3;
        bsplit(v.x, h0, l0); bsplit(v.y, h1, l1);
        bsplit(v.z, h2, l2); bsplit(v.w, h3, l3);
        uint32_t a0 = amap16(mr, c4), a1 = amap16(mr, c4 + 2);
        *(__nv_bfloat162*)(sm + CB + P_S0H + a0) = __halves2bfloat162(h0, h1);
        *(__nv_bfloat162*)(sm + CB + P_S0L + a0) = __halves2bfloat162(l0, l1);
        *(__nv_bfloat162*)(sm + CB + P_S0H + a1) = __halves2bfloat162(h2, h3);
        *(__nv_bfloat162*)(sm + CB + P_S0L + a1) = __halves2bfloat162(l2, l3);
        int rowb = (mr >= 64) ? 64 : 0, colr = mr & 63;
        *(__nv_bfloat16*)(sm + CB + P_S1H + amap16(rowb + c4 + 0, colr)) = h0;
        *(__nv_bfloat16*)(sm + CB + P_S1L + amap16(rowb + c4 + 0, colr)) = l0;
        *(__nv_bfloat16*)(sm + CB + P_S1H + amap16(rowb + c4 + 1, colr)) = h1;
        *(__nv_bfloat16*)(sm + CB + P_S1L + amap16(rowb + c4 + 1, colr)) = l1;
        *(__nv_bfloat16*)(sm + CB + P_S1H + amap16(rowb + c4 + 2, colr)) = h2;
        *(__nv_bfloat16*)(sm + CB + P_S1L + amap16(rowb + c4 + 2, colr)) = l2;
        *(__nv_bfloat16*)(sm + CB + P_S1H + amap16(rowb + c4 + 3, colr)) = h3;
        *(__nv_bfloat16*)(sm + CB + P_S1L + amap16(rowb + c4 + 3, colr)) = l3;
    }
    FENCE_PROXY_ASYNC();
    __syncthreads();

    // ===== per-chain pipeline (independent below this line) =====
    int ph = 0;
    // G1: D0 = x*Su ; G3: D1 = xT*Su (= x10^T)
    if (wl == 0 && elect1()) {
        gemm3(D0, sb + S0H, sb + S0L, sb + SM_BUH, sb + SM_BUL);
        gemm3(D1, sb + S1H, sb + S1L, sb + SM_BUH, sb + SM_BUL);
        TCGEN05_COMMIT(MB);
    }
    MBARRIER_WAIT_PARITY(MB, ph); ph ^= 1;
    TCGEN05_FENCE_AFTER();

    if (wl < 4) {
        // E1: a01 = silu(D0) -> S1 hi/lo (xT dead), 64 cols per warp
#pragma unroll
        for (int hblk = 0; hblk < 2; hblk++) {
            uint32_t r[32];
            LDTM_X32(r, D0 + 32 * hblk);
            TCGEN05_WAIT_LD();
#pragma unroll
            for (int t = 0; t < 16; t++) {
                float v0 = silu_f(__uint_as_float(r[2 * t]));
                float v1 = silu_f(__uint_as_float(r[2 * t + 1]));
                __nv_bfloat16 h0, l0, h1, l1;
                bsplit(v0, h0, l0); bsplit(v1, h1, l1);
                uint32_t a = amap16(mg, 32 * hblk + 2 * t);
                *(__nv_bfloat162*)(sm + S1H + a) = __halves2bfloat162(h0, h1);
                *(__nv_bfloat162*)(sm + S1L + a) = __halves2bfloat162(l0, l1);
            }
        }
    } else {
        // E3: de-transpose D1 (x10^T) -> S2 row-form hi/lo
        int img64 = (mg >= 64) ? 64 : 0, colm = mg & 63;
#pragma unroll
        for (int hblk = 0; hblk < 2; hblk++) {
            uint32_t r[32];
            LDTM_X32(r, D1 + 32 * hblk);
            TCGEN05_WAIT_LD();
#pragma unroll
            for (int c = 0; c < 32; c++) {
                __nv_bfloat16 h, l;
                bsplit(__uint_as_float(r[c]), h, l);
                uint32_t a = amap16(img64 + 32 * hblk + c, colm);
                *(__nv_bfloat16*)(sm + S2H + a) = h;
                *(__nv_bfloat16*)(sm + S2L + a) = l;
            }
        }
    }
    TCGEN05_FENCE_BEFORE();
    FENCE_PROXY_ASYNC();
    CHAIN_BAR(chain);

    // G2: D0 = a01*Sd ; G4: D1 = x10*Su
    if (wl == 0 && elect1()) {
        gemm3(D0, sb + S1H, sb + S1L, sb + SM_BDH, sb + SM_BDL);
        gemm3(D1, sb + S2H, sb + S2L, sb + SM_BUH, sb + SM_BUL);
        TCGEN05_COMMIT(MB);
    }
    MBARRIER_WAIT_PARITY(MB, ph); ph ^= 1;
    TCGEN05_FENCE_AFTER();

    if (wl < 4) {
        // E2: R0 = silu(x) + D0, in place in S0 hi/lo
#pragma unroll
        for (int hblk = 0; hblk < 2; hblk++) {
            uint32_t r[32];
            LDTM_X32(r, D0 + 32 * hblk);
            TCGEN05_WAIT_LD();
#pragma unroll
            for (int t = 0; t < 16; t++) {
                uint32_t a = amap16(mg, 32 * hblk + 2 * t);
                __nv_bfloat162 xh = *(__nv_bfloat162*)(sm + S0H + a);
                __nv_bfloat162 xl = *(__nv_bfloat162*)(sm + S0L + a);
                float x0 = __bfloat162float(xh.x) + __bfloat162float(xl.x);
                float x1 = __bfloat162float(xh.y) + __bfloat162float(xl.y);
                float v0 = silu_f(x0) + __uint_as_float(r[2 * t]);
                float v1 = silu_f(x1) + __uint_as_float(r[2 * t + 1]);
                __nv_bfloat16 h0, l0, h1, l1;
                bsplit(v0, h0, l0); bsplit(v1, h1, l1);
                *(__nv_bfloat162*)(sm + S0H + a) = __halves2bfloat162(h0, h1);
                *(__nv_bfloat162*)(sm + S0L + a) = __halves2bfloat162(l0, l1);
            }
        }
    } else {
        // E4: a11 = silu(D1) -> S1 hi/lo (a01 dead)
#pragma unroll
        for (int hblk = 0; hblk < 2; hblk++) {
            uint32_t r[32];
            LDTM_X32(r, D1 + 32 * hblk);
            TCGEN05_WAIT_LD();
#pragma unroll
            for (int t = 0; t < 16; t++) {
                float v0 = silu_f(__uint_as_float(r[2 * t]));
                float v1 = silu_f(__uint_as_float(r[2 * t + 1]));
                __nv_bfloat16 h0, l0, h1, l1;
                bsplit(v0, h0, l0); bsplit(v1, h1, l1);
                uint32_t a = amap16(mg, 32 * hblk + 2 * t);
                *(__nv_bfloat162*)(sm + S1H + a) = __halves2bfloat162(h0, h1);
                *(__nv_bfloat162*)(sm + S1L + a) = __halves2bfloat162(l0, l1);
            }
        }
    }
    TCGEN05_FENCE_BEFORE();
    FENCE_PROXY_ASYNC();
    CHAIN_BAR(chain);

    // G5: D0 = a11*Sd
    if (wl == 0 && elect1()) {
        gemm3(D0, sb + S1H, sb + S1L, sb + SM_BDH, sb + SM_BDL);
        TCGEN05_COMMIT(MB);
    }
    MBARRIER_WAIT_PARITY(MB, ph); ph ^= 1;
    TCGEN05_FENCE_AFTER();

    // E5 (all 8 warps, 32 cols each): W = D0 + silu(x10); store W^T -> S1 hi/lo
    {
        uint32_t r[32];
        LDTM_X32(r, D0 + cbg);
        TCGEN05_WAIT_LD();
        int img64 = (mg >= 64) ? 64 : 0, colm = mg & 63;
#pragma unroll
        for (int c = 0; c < 32; c++) {
            float x10v = bjoin(sm, S2H, S2L, amap16(mg, cbg + c));
            float wv = __uint_as_float(r[c]) + silu_f(x10v);
            __nv_bfloat16 h, l;
            bsplit(wv, h, l);
            uint32_t a = amap16(img64 + cbg + c, colm);
            *(__nv_bfloat16*)(sm + S1H + a) = h;
            *(__nv_bfloat16*)(sm + S1L + a) = l;
        }
    }
    TCGEN05_FENCE_BEFORE();
    FENCE_PROXY_ASYNC();
    CHAIN_BAR(chain);

    // G6: D1 = W^T*Sd  ( = (Su*W)^T )
    if (wl == 0 && elect1()) {
        gemm3(D1, sb + S1H, sb + S1L, sb + SM_BDH, sb + SM_BDL);
        TCGEN05_COMMIT(MB);
    }
    MBARRIER_WAIT_PARITY(MB, ph); ph ^= 1;
    TCGEN05_FENCE_AFTER();

    // E6 (all 8 warps): y = 0.25*(R0 + branch2), branch2[j][colm] = D1[img64+colm... row mg][j]
    {
        uint32_t r[32];
        LDTM_X32(r, D1 + cbg);
        TCGEN05_WAIT_LD();
        int img = (mg >= 64) ? 1 : 0, colm = mg & 63;
        float* yg = y + ((size_t)blockIdx.x * 4 + chain * 2 + img) * 4096;
#pragma unroll
        for (int c = 0; c < 32; c++) {
            int j = cbg + c;
            float r0 = bjoin(sm, S0H, S0L, amap16(img * 64 + j, colm));
            yg[j * 64 + colm] = 0.25f * (__uint_as_float(r[c]) + r0);
        }
    }
    TCGEN05_FENCE_BEFORE();
    __syncthreads();
    if (tid == 0) { MBARRIER_INVAL(sb + SM_MBAR0); MBARRIER_INVAL(sb + SM_MBAR0 + 16); }
    __syncthreads();
    if (w == 0) {
        TCGEN05_RELINQ();
        TCGEN05_DEALLOC(tb, 256);
    }

#else
    // ===== compact FFMA fallback (compat PTX pass only; never runs on GB300) =====
#define FS 65
    extern __shared__ float fsm[];
    float* Su = fsm;
    float* Sd = Su + 64 * FS;
    float* bx = Sd + 64 * FS;
    float* t1 = bx + 64 * FS;
    float* t2 = t1 + 64 * FS;
    float* s64 = t2 + 64 * FS;
    const int tid = threadIdx.x;
    if (tid < 64) {
        float q = (float)(2 * tid + 1);
        s64[tid] = sinpif(63.0f * q * (1.0f / 128.0f)) /
                   (64.0f * sinpif(q * (1.0f / 128.0f)));
    }
    __syncthreads();
    for (int idx = tid; idx < 4096; idx += 512) {
        int n = idx >> 6, j = idx & 63;
        Su[n * FS + j] = s64[(j - n) & 63];
        Sd[n * FS + j] = s64[(j - n - 1) & 63];
    }
    __syncthreads();
    for (int img = 0; img < 4; img++) {
        const float* xin = x + ((size_t)blockIdx.x * 4 + img) * 4096;
        float* yout      = y + ((size_t)blockIdx.x * 4 + img) * 4096;
        for (int idx = tid; idx < 4096; idx += 512)
            bx[(idx >> 6) * FS + (idx & 63)] = xin[idx];
        __syncthreads();
        float acc[8];
        for (int e = 0; e < 8; e++) {        // t1 = silu(bx*Su)
            int idx = tid + 512 * e, n = idx >> 6, j = idx & 63;
            float s = 0.f;
            for (int k = 0; k < 64; k++) s = fmaf(bx[n * FS + k], Su[k * FS + j], s);
            t1[n * FS + j] = silu_f(s);
        }
        __syncthreads();
        for (int e = 0; e < 8; e++) {        // acc = silu(bx)+t1*Sd ; t2 = Su^T*bx
            int idx = tid + 512 * e, n = idx >> 6, j = idx & 63;
            float s = silu_f(bx[n * FS + j]), u = 0.f;
            for (int k = 0; k < 64; k++) {
                s = fmaf(t1[n * FS + k], Sd[k * FS + j], s);
                u = fmaf(Su[k * FS + n], bx[k * FS + j], u);
            }
            acc[e] = s;
            t2[n * FS + j] = u;
        }
        __syncthreads();
        for (int e = 0; e < 8; e++) {        // t1 = silu(t2*Su)
            int idx = tid + 512 * e, n = idx >> 6, j = idx & 63;
            float s = 0.f;
            for (int k = 0; k < 64; k++) s = fmaf(t2[n * FS + k], Su[k * FS + j], s);
            t1[n * FS + j] = silu_f(s);
        }
        __syncthreads();
        for (int e = 0; e < 8; e++) {        // bx = t1*Sd + silu(t2)
            int idx = tid + 512 * e, n = idx >> 6, j = idx & 63;
            float s = silu_f(t2[n * FS + j]);
            for (int k = 0; k < 64; k++) s = fmaf(t1[n * FS + k], Sd[k * FS + j], s);
            bx[n * FS + j] = s;
        }
        __syncthreads();
        for (int e = 0; e < 8; e++) {        // acc += Su*bx ; write
            int idx = tid + 512 * e, n = idx >> 6, j = idx & 63;
            float s = acc[e];
            for (int k = 0; k < 64; k++) s = fmaf(Su[n * FS + k], bx[k * FS + j], s);
            yout[idx] = 0.25f * s;
        }
        __syncthreads();
    }
#endif
}

extern "C" void kernel_launch(void* const* d_in, const int* in_sizes, int n_in,
                              void* d_out, int out_size) {
    const float* x = (const float*)d_in[0];
    float* y = (float*)d_out;
    const int n_img = in_sizes[0] / 4096;      // 2048
    cudaFuncSetAttribute(warped_kernel,
                         cudaFuncAttributeMaxDynamicSharedMemorySize, SM_TOTAL);
    warped_kernel<<<n_img / 4, 512, SM_TOTAL>>>(x, y);
}